// round 13
// baseline (speedup 1.0000x reference)
#include <cuda_runtime.h>
#include <cuda_fp16.h>
#include <math.h>

#define NN 20000
#define FF 8
#define PP 12
#define OO 32
#define EE 320000
#define FP 96           // F*P floats per node row
#define RH 128          // padded fp16 row stride (256B-aligned rows)
#define SLOTS 96        // max in-degree slots (Poisson(16); guarded)
#define NSM 148
#define NBPS 3
#define NBLK (NSM * NBPS)            // 444 blocks, all co-resident
#define NTHR 256
#define WPB (NTHR / 32)              // 8 warps per block
#define FULL 0xffffffffu

// ---- scratch (static device globals; no allocation allowed) ----
__device__ int      g_cnt[NN];            // in-degree (atomic counters)
__device__ int      g_col[NN * SLOTS];    // slotted adjacency: srcs per dst
__device__ float    g_dinv[NN];           // (in_deg + 1)^-1/2
__device__ __align__(16) __half g_xh[NN * RH];  // fp16 copy of x, padded rows
__device__ float    g_cwz[FF * OO];       // fused Wz @ Lz^T
__device__ float    g_cwh[FF * OO];       // fused Wh @ Lh^T
__device__ float    g_cbz[OO];
__device__ float    g_cbh[OO];
__device__ float    g_probs[PP];
__device__ unsigned g_node_ctr;           // P3 dynamic work counter (reset in P0)
__device__ unsigned g_bar[3];             // monotonic barrier counters (never reset)

// Monotonic grid barrier: all NBLK blocks co-resident (3/SM via launch bounds).
__device__ __forceinline__ void grid_barrier(int id) {
    __syncthreads();
    if (threadIdx.x == 0) {
        __threadfence();                                      // release
        unsigned arrived = atomicAdd(&g_bar[id], 1u) + 1u;
        unsigned target  = ((arrived + NBLK - 1u) / NBLK) * NBLK;
        while (*(volatile unsigned*)&g_bar[id] < target) { }
        __threadfence();                                      // acquire
    }
    __syncthreads();
}

// Packed fp32x2 helpers (Blackwell FFMA2 — only reachable via PTX)
__device__ __forceinline__ unsigned long long pack2(float lo, float hi) {
    unsigned long long r;
    asm("mov.b64 %0, {%1, %2};" : "=l"(r) : "f"(lo), "f"(hi));
    return r;
}
__device__ __forceinline__ void unpack2(unsigned long long v, float& lo, float& hi) {
    asm("mov.b64 {%0, %1}, %2;" : "=f"(lo), "=f"(hi) : "l"(v));
}
__device__ __forceinline__ unsigned long long ffma2(
        unsigned long long a, unsigned long long b, unsigned long long c) {
    unsigned long long d;
    asm("fma.rn.f32x2 %0, %1, %2, %3;" : "=l"(d) : "l"(a), "l"(b), "l"(c));
    return d;
}
// HW tanh (MUFU.TANH), rel err ~1e-5 — far inside the 1e-3 budget
__device__ __forceinline__ float htanh(float x) {
    float r;
    asm("tanh.approx.f32 %0, %1;" : "=f"(r) : "f"(x));
    return r;
}

// Per-node prologue state, loaded one pipeline stage ahead.
struct Prolog {
    int   deg;     // clamped degree
    float di;      // (deg+1)^-1/2 for the node
    int   ci;      // lane's slot col (clamped-valid, masked later)
    float wv;      // dinv[ci] (masked later)
};

__device__ __forceinline__ Prolog load_prolog(int node, int lane) {
    Prolog p;
    int   deg = __ldg(&g_cnt[node]);
    p.di  = __ldg(&g_dinv[node]);
    int   raw = __ldg(&g_col[node * SLOTS + lane]);   // always in-bounds (SLOTS>=32)
    int   cl  = raw < 0 ? 0 : (raw >= NN ? NN - 1 : raw);
    float wv  = __ldg(&g_dinv[cl]);
    if (deg > SLOTS) deg = SLOTS;
    p.deg = deg;
    p.ci  = (lane < deg) ? cl : 0;
    p.wv  = (lane < deg) ? wv : 0.f;
    return p;
}

// fp16 row fetch: lane < 24, each lane owns 8 bytes (4 halves) of the 192B row
__device__ __forceinline__ void fma_row_h(
        float4& acc, float w, int src, int lane) {
    uint2 u = __ldg((const uint2*)(g_xh + (size_t)src * RH) + lane);
    float2 a = __half22float2(*(const __half2*)&u.x);
    float2 b = __half22float2(*(const __half2*)&u.y);
    acc.x = fmaf(w, a.x, acc.x); acc.y = fmaf(w, a.y, acc.y);
    acc.z = fmaf(w, b.x, acc.z); acc.w = fmaf(w, b.y, acc.w);
}

__global__ void __launch_bounds__(NTHR, NBPS) fused_kernel(
        const float* __restrict__ x,
        const int*   __restrict__ ei,
        const float* __restrict__ Wz,  const float* __restrict__ bz,
        const float* __restrict__ Wh,  const float* __restrict__ bh,
        const float* __restrict__ lzw, const float* __restrict__ lzb,
        const float* __restrict__ lhw, const float* __restrict__ lhb,
        const float* __restrict__ att,
        const float* __restrict__ out_w, const float* __restrict__ out_b,
        float* __restrict__ out) {
    const int t    = threadIdx.x;
    const int lane = t & 31;
    const int warp = t >> 5;                 // 0..7
    const int gid  = blockIdx.x * NTHR + t;
    const int T    = NBLK * NTHR;

    __shared__ float buf[WPB][2][FP];        // GRU staging, per warp, 2 nodes
    __shared__ float sow[PP * OO];           // staged out_w
    __shared__ float sob[PP];                // staged out_b
    __shared__ float sp2[PP];                // 0.5 * softmax(att)

    // ------- P0: zero counters + fp16 convert of x + fold weights ----------
    for (int j = gid; j < NN; j += T) g_cnt[j] = 0;

    // x (fp32, [NN][96]) -> g_xh (fp16, [NN][128] padded). Coalesced float2 in,
    // half2 out. ~1M float2 over 113k threads ≈ 9 iterations.
    {
        const float2* x2 = (const float2*)x;
        __half2* xh2 = (__half2*)g_xh;
        for (int j = gid; j < NN * (FP / 2); j += T) {
            int r  = j / (FP / 2);
            int c2 = j - r * (FP / 2);
            xh2[r * (RH / 2) + c2] = __float22half2_rn(x2[j]);
        }
    }

    if (blockIdx.x == 0) {                   // W'_z[f][o] = sum_k Wz[f][k]*lzw[o][k]
        int f = t >> 5, o = t & 31;
        float s = 0.f;
        #pragma unroll
        for (int k = 0; k < 32; ++k) s = fmaf(Wz[f * 32 + k], lzw[o * 64 + k], s);
        g_cwz[t] = s;
    } else if (blockIdx.x == 1) {            // W'_h
        int f = t >> 5, o = t & 31;
        float s = 0.f;
        #pragma unroll
        for (int k = 0; k < 32; ++k) s = fmaf(Wh[f * 32 + k], lhw[o * 64 + k], s);
        g_cwh[t] = s;
    } else if (blockIdx.x == 2) {
        if (t < 32) {                        // b'_z
            float s = lzb[t];
            #pragma unroll
            for (int k = 0; k < 32; ++k) s = fmaf(bz[k], lzw[t * 64 + k], s);
            g_cbz[t] = s;
        } else if (t < 64) {                 // b'_h
            int o = t - 32;
            float s = lhb[o];
            #pragma unroll
            for (int k = 0; k < 32; ++k) s = fmaf(bh[k], lhw[o * 64 + k], s);
            g_cbh[o] = s;
        } else if (t == 64) {                // softmax over 12 logits
            float m = att[0];
            for (int p = 1; p < PP; ++p) m = fmaxf(m, att[p]);
            float e[PP], sum = 0.f;
            for (int p = 0; p < PP; ++p) { e[p] = __expf(att[p] - m); sum += e[p]; }
            float inv = 1.f / sum;
            for (int p = 0; p < PP; ++p) g_probs[p] = e[p] * inv;
        }
        if (t == 65) g_node_ctr = 0;         // reset P3 work counter
    }
    grid_barrier(0);

    // ---------------- P1: single-pass slotted scatter -----------------------
    {
        const int4* s4p = (const int4*)ei;
        const int4* d4p = (const int4*)(ei + EE);
        for (int q = gid; q < EE / 4; q += T) {
            int4 s4 = s4p[q];
            int4 d4 = d4p[q];
            int p0 = atomicAdd(&g_cnt[d4.x], 1);
            int p1 = atomicAdd(&g_cnt[d4.y], 1);
            int p2 = atomicAdd(&g_cnt[d4.z], 1);
            int p3 = atomicAdd(&g_cnt[d4.w], 1);
            if (p0 < SLOTS) g_col[d4.x * SLOTS + p0] = s4.x;
            if (p1 < SLOTS) g_col[d4.y * SLOTS + p1] = s4.y;
            if (p2 < SLOTS) g_col[d4.z * SLOTS + p2] = s4.z;
            if (p3 < SLOTS) g_col[d4.w * SLOTS + p3] = s4.w;
        }
    }
    grid_barrier(1);

    // ---------------- P2: dinv = (deg+1)^-1/2 ------------------------------
    for (int j = gid; j < NN; j += T)
        g_dinv[j] = rsqrtf((float)(__ldcg(&g_cnt[j]) + 1));
    grid_barrier(2);

    // ---------------- P3: software-pipelined gather + GRU + readout --------
    {
        if (t < PP) sp2[t] = 0.5f * g_probs[t];   // fold sigmoid's 0.5
        if (t < PP) sob[t] = out_b[t];
        for (int j = t; j < PP * OO; j += NTHR) sow[j] = out_w[j];
        __syncthreads();

        float wzr[FF], whr[FF];
        #pragma unroll
        for (int f = 0; f < FF; ++f) {
            wzr[f] = g_cwz[f * OO + lane];
            whr[f] = g_cwh[f * OO + lane];
        }
        const float bz_ = g_cbz[lane];
        const float bh_ = g_cbh[lane];

        int base;
        if (lane == 0) base = (int)atomicAdd(&g_node_ctr, 2u);
        base = __shfl_sync(FULL, base, 0);
        Prolog pA, pB;
        if (base < NN) {                     // NN even -> base+1 valid too
            pA = load_prolog(base, lane);
            pB = load_prolog(base + 1, lane);
        }

        while (base < NN) {
            const int nA = base, nB = base + 1;

            // -------- gather both nodes (fp16 rows, prologue resolved) -----
            #pragma unroll
            for (int i = 0; i < 2; ++i) {
                const Prolog& pr = (i == 0) ? pA : pB;
                const int node = (i == 0) ? nA : nB;
                float4 acc = make_float4(0.f, 0.f, 0.f, 0.f);

                int ci = pr.ci; float wv = pr.wv;
                int deg4 = (pr.deg + 3) & ~3;
                for (int b = 0; b < deg4; b += 32) {
                    if (b) {                                  // rare: deg > 32
                        int raw = __ldg(&g_col[node * SLOTS + b + lane]);
                        int cl = raw < 0 ? 0 : (raw >= NN ? NN - 1 : raw);
                        float w2 = __ldg(&g_dinv[cl]);
                        ci = (b + lane < pr.deg) ? cl : 0;
                        wv = (b + lane < pr.deg) ? w2 : 0.f;
                    }
                    int nb = deg4 - b; if (nb > 32) nb = 32;
                    for (int k = 0; k < nb; k += 4) {
                        int   s0 = __shfl_sync(FULL, ci, k);
                        int   s1 = __shfl_sync(FULL, ci, k + 1);
                        int   s2 = __shfl_sync(FULL, ci, k + 2);
                        int   s3 = __shfl_sync(FULL, ci, k + 3);
                        float w0 = __shfl_sync(FULL, wv, k);
                        float w1 = __shfl_sync(FULL, wv, k + 1);
                        float w2 = __shfl_sync(FULL, wv, k + 2);
                        float w3 = __shfl_sync(FULL, wv, k + 3);
                        if (lane < 24) {
                            fma_row_h(acc, w0, s0, lane);
                            fma_row_h(acc, w1, s1, lane);
                            fma_row_h(acc, w2, s2, lane);
                            fma_row_h(acc, w3, s3, lane);
                        }
                    }
                }
                if (lane < 24) {              // agg = di*(acc + di*x_self), fp32 self
                    float di = pr.di;
                    float4 xv = __ldg((const float4*)(x + (size_t)node * FP) + lane);
                    acc.x = di * fmaf(di, xv.x, acc.x);
                    acc.y = di * fmaf(di, xv.y, acc.y);
                    acc.z = di * fmaf(di, xv.z, acc.z);
                    acc.w = di * fmaf(di, xv.w, acc.w);
                    ((float4*)buf[warp][i])[lane] = acc;
                }
            }
            __syncwarp();

            // -------- pop + prefetch NEXT pair BEFORE the GRU compute ------
            int nbase;
            if (lane == 0) nbase = (int)atomicAdd(&g_node_ctr, 2u);
            nbase = __shfl_sync(FULL, nbase, 0);
            if (nbase < NN) {
                pA = load_prolog(nbase, lane);       // hidden by GRU below
                pB = load_prolog(nbase + 1, lane);
            }

            // -------- GRU + readout for both nodes (pure compute) ----------
            #pragma unroll
            for (int i = 0; i < 2; ++i) {
                const float* bw = buf[warp][i];
                unsigned long long zp[PP / 2], hp[PP / 2];
                {
                    unsigned long long bz2 = pack2(bz_, bz_);
                    unsigned long long bh2 = pack2(bh_, bh_);
                    #pragma unroll
                    for (int q = 0; q < PP / 2; ++q) { zp[q] = bz2; hp[q] = bh2; }
                }
                #pragma unroll
                for (int f = 0; f < FF; ++f) {
                    unsigned long long wz2 = pack2(wzr[f], wzr[f]);
                    unsigned long long wh2 = pack2(whr[f], whr[f]);
                    #pragma unroll
                    for (int q = 0; q < PP / 2; ++q) {
                        unsigned long long v2 =
                            *(const unsigned long long*)&bw[f * PP + 2 * q];
                        zp[q] = ffma2(v2, wz2, zp[q]);
                        hp[q] = ffma2(v2, wh2, hp[q]);
                    }
                }
                // probs*(1-Z)*tanh(h), Z = 0.5 + 0.5*tanh(z/2)
                float hacc = 0.f;
                #pragma unroll
                for (int q = 0; q < PP / 2; ++q) {
                    float z0, z1, h0, h1;
                    unpack2(zp[q], z0, z1);
                    unpack2(hp[q], h0, h1);
                    float tz0 = htanh(0.5f * z0);
                    float tz1 = htanh(0.5f * z1);
                    float th0 = htanh(h0);
                    float th1 = htanh(h1);
                    hacc = fmaf(sp2[2 * q],     (1.f - tz0) * th0, hacc);
                    hacc = fmaf(sp2[2 * q + 1], (1.f - tz1) * th1, hacc);
                }
                float hr = fmaxf(hacc, 0.f);     // relu

                float myout = 0.f;
                #pragma unroll
                for (int p = 0; p < PP; ++p) {
                    float v = hr * sow[p * OO + lane];
                    v += __shfl_xor_sync(FULL, v, 16);
                    v += __shfl_xor_sync(FULL, v, 8);
                    v += __shfl_xor_sync(FULL, v, 4);
                    v += __shfl_xor_sync(FULL, v, 2);
                    v += __shfl_xor_sync(FULL, v, 1);
                    if (lane == p) myout = v + sob[p];
                }
                if (lane < PP) out[(base + i) * PP + lane] = myout;
            }
            __syncwarp();                    // buf reads done before next pair
            base = nbase;
        }
    }
}

// ---------------------------------------------------------------------------
extern "C" void kernel_launch(void* const* d_in, const int* in_sizes, int n_in,
                              void* d_out, int out_size) {
    const float* x    = (const float*)d_in[0];
    const int*   ei   = (const int*)  d_in[1];
    const float* Wz   = (const float*)d_in[2];
    const float* bz   = (const float*)d_in[3];
    // d_in[4], d_in[5]: Wr, br — dead code (H == 0 kills the reset gate)
    const float* Wh   = (const float*)d_in[6];
    const float* bh   = (const float*)d_in[7];
    const float* lzw  = (const float*)d_in[8];
    const float* lzb  = (const float*)d_in[9];
    // d_in[10], d_in[11]: lr_w, lr_b — unused
    const float* lhw  = (const float*)d_in[12];
    const float* lhb  = (const float*)d_in[13];
    const float* att  = (const float*)d_in[14];
    const float* outw = (const float*)d_in[15];
    const float* outb = (const float*)d_in[16];
    float* out = (float*)d_out;

    fused_kernel<<<NBLK, NTHR>>>(x, ei, Wz, bz, Wh, bh, lzw, lzb, lhw, lhb,
                                 att, outw, outb, out);
}

// round 14
// speedup vs baseline: 1.1550x; 1.1550x over previous
#include <cuda_runtime.h>
#include <math.h>

#define NN 20000
#define FF 8
#define PP 12
#define OO 32
#define EE 320000
#define FP 96           // F*P floats per node row
#define SLOTS 96        // max in-degree slots (Poisson(16); guarded)
#define NSM 148
#define NBPS 3
#define NBLK (NSM * NBPS)            // 444 blocks, all co-resident
#define NTHR 256
#define WPB (NTHR / 32)              // 8 warps per block
#define SOWP 36                      // padded out_w row stride (bank-safe, 16B-aligned)
#define FULL 0xffffffffu

// ---- scratch (static device globals; no allocation allowed) ----
__device__ int      g_cnt[NN];            // in-degree (atomic counters)
__device__ int      g_col[NN * SLOTS];    // slotted adjacency: srcs per dst
__device__ float    g_cwz[FF * OO];       // fused Wz @ Lz^T
__device__ float    g_cwh[FF * OO];       // fused Wh @ Lh^T
__device__ float    g_cbz[OO];
__device__ float    g_cbh[OO];
__device__ float    g_probs[PP];
__device__ unsigned g_node_ctr;           // P3 dynamic work counter (reset in P0)
__device__ unsigned g_bar[2];             // monotonic barrier counters (never reset)

// Monotonic grid barrier: all NBLK blocks co-resident (3/SM via launch bounds).
__device__ __forceinline__ void grid_barrier(int id) {
    __syncthreads();
    if (threadIdx.x == 0) {
        __threadfence();                                      // release
        unsigned arrived = atomicAdd(&g_bar[id], 1u) + 1u;
        unsigned target  = ((arrived + NBLK - 1u) / NBLK) * NBLK;
        while (*(volatile unsigned*)&g_bar[id] < target) { }
        __threadfence();                                      // acquire
    }
    __syncthreads();
}

// Packed fp32x2 helpers (Blackwell FFMA2 — only reachable via PTX)
__device__ __forceinline__ unsigned long long pack2(float lo, float hi) {
    unsigned long long r;
    asm("mov.b64 %0, {%1, %2};" : "=l"(r) : "f"(lo), "f"(hi));
    return r;
}
__device__ __forceinline__ void unpack2(unsigned long long v, float& lo, float& hi) {
    asm("mov.b64 {%0, %1}, %2;" : "=f"(lo), "=f"(hi) : "l"(v));
}
__device__ __forceinline__ unsigned long long ffma2(
        unsigned long long a, unsigned long long b, unsigned long long c) {
    unsigned long long d;
    asm("fma.rn.f32x2 %0, %1, %2, %3;" : "=l"(d) : "l"(a), "l"(b), "l"(c));
    return d;
}
// HW tanh (MUFU.TANH), rel err ~1e-5 — far inside the 1e-3 budget
__device__ __forceinline__ float htanh(float x) {
    float r;
    asm("tanh.approx.f32 %0, %1;" : "=f"(r) : "f"(x));
    return r;
}

// Per-node prologue state, loaded one pipeline stage ahead.
// dinv values are computed from cnt via MUFU.RSQ (no g_dinv array, no P2 phase).
struct Prolog {
    int    deg;     // clamped degree
    float  di;      // (deg+1)^-1/2 for the node
    int    ci;      // lane's slot col (clamped-valid, masked later)
    float  wv;      // rsqrt(cnt[ci]+1) (masked later)
    float4 xv;      // self row chunk (lane < 24)
};

__device__ __forceinline__ Prolog load_prolog(
        int node, int lane, const float* __restrict__ x) {
    Prolog p;
    int   deg = __ldg(&g_cnt[node]);
    int   raw = __ldg(&g_col[node * SLOTS + lane]);   // always in-bounds (SLOTS>=32)
    int   cl  = raw < 0 ? 0 : (raw >= NN ? NN - 1 : raw);
    int   cc  = __ldg(&g_cnt[cl]);
    p.xv = (lane < 24) ? __ldg((const float4*)(x + (size_t)node * FP) + lane)
                       : make_float4(0.f, 0.f, 0.f, 0.f);
    p.di = rsqrtf((float)(deg + 1));
    float wv = rsqrtf((float)(cc + 1));
    if (deg > SLOTS) deg = SLOTS;
    p.deg = deg;
    p.ci  = (lane < deg) ? cl : 0;
    p.wv  = (lane < deg) ? wv : 0.f;
    return p;
}

__global__ void __launch_bounds__(NTHR, NBPS) fused_kernel(
        const float* __restrict__ x,
        const int*   __restrict__ ei,
        const float* __restrict__ Wz,  const float* __restrict__ bz,
        const float* __restrict__ Wh,  const float* __restrict__ bh,
        const float* __restrict__ lzw, const float* __restrict__ lzb,
        const float* __restrict__ lhw, const float* __restrict__ lhb,
        const float* __restrict__ att,
        const float* __restrict__ out_w, const float* __restrict__ out_b,
        float* __restrict__ out) {
    const int t    = threadIdx.x;
    const int lane = t & 31;
    const int warp = t >> 5;                 // 0..7
    const int gid  = blockIdx.x * NTHR + t;
    const int T    = NBLK * NTHR;

    __shared__ __align__(16) float buf[WPB][2][FP];  // GRU staging, per warp, 2 nodes
    __shared__ __align__(16) float hrb[WPB][2][OO];  // hr staging for readout
    __shared__ __align__(16) float sow[PP * SOWP];   // padded out_w
    __shared__ float sob[PP];                        // staged out_b
    __shared__ float sp2[PP];                        // 0.5 * softmax(att)

    // ---------------- P0: zero counters + fold weights (blocks 0..2) -------
    for (int j = gid; j < NN; j += T) g_cnt[j] = 0;

    if (blockIdx.x == 0) {                   // W'_z[f][o] = sum_k Wz[f][k]*lzw[o][k]
        int f = t >> 5, o = t & 31;
        float s = 0.f;
        #pragma unroll
        for (int k = 0; k < 32; ++k) s = fmaf(Wz[f * 32 + k], lzw[o * 64 + k], s);
        g_cwz[t] = s;
    } else if (blockIdx.x == 1) {            // W'_h
        int f = t >> 5, o = t & 31;
        float s = 0.f;
        #pragma unroll
        for (int k = 0; k < 32; ++k) s = fmaf(Wh[f * 32 + k], lhw[o * 64 + k], s);
        g_cwh[t] = s;
    } else if (blockIdx.x == 2) {
        if (t < 32) {                        // b'_z
            float s = lzb[t];
            #pragma unroll
            for (int k = 0; k < 32; ++k) s = fmaf(bz[k], lzw[t * 64 + k], s);
            g_cbz[t] = s;
        } else if (t < 64) {                 // b'_h
            int o = t - 32;
            float s = lhb[o];
            #pragma unroll
            for (int k = 0; k < 32; ++k) s = fmaf(bh[k], lhw[o * 64 + k], s);
            g_cbh[o] = s;
        } else if (t == 64) {                // softmax over 12 logits
            float m = att[0];
            for (int p = 1; p < PP; ++p) m = fmaxf(m, att[p]);
            float e[PP], sum = 0.f;
            for (int p = 0; p < PP; ++p) { e[p] = __expf(att[p] - m); sum += e[p]; }
            float inv = 1.f / sum;
            for (int p = 0; p < PP; ++p) g_probs[p] = e[p] * inv;
        }
        if (t == 65) g_node_ctr = 0;         // reset P3 work counter
    }
    grid_barrier(0);

    // ---------------- P1: single-pass slotted scatter -----------------------
    {
        const int4* s4p = (const int4*)ei;
        const int4* d4p = (const int4*)(ei + EE);
        for (int q = gid; q < EE / 4; q += T) {
            int4 s4 = s4p[q];
            int4 d4 = d4p[q];
            int p0 = atomicAdd(&g_cnt[d4.x], 1);
            int p1 = atomicAdd(&g_cnt[d4.y], 1);
            int p2 = atomicAdd(&g_cnt[d4.z], 1);
            int p3 = atomicAdd(&g_cnt[d4.w], 1);
            if (p0 < SLOTS) g_col[d4.x * SLOTS + p0] = s4.x;
            if (p1 < SLOTS) g_col[d4.y * SLOTS + p1] = s4.y;
            if (p2 < SLOTS) g_col[d4.z * SLOTS + p2] = s4.z;
            if (p3 < SLOTS) g_col[d4.w * SLOTS + p3] = s4.w;
        }
    }
    grid_barrier(1);

    // ---------------- P3: software-pipelined gather + GRU + readout --------
    {
        if (t < PP) sp2[t] = 0.5f * g_probs[t];   // fold sigmoid's 0.5
        if (t < PP) sob[t] = out_b[t];
        for (int j = t; j < PP * OO; j += NTHR) {
            int p = j >> 5, k = j & 31;
            sow[p * SOWP + k] = out_w[j];
        }
        __syncthreads();

        float wzr[FF], whr[FF];
        #pragma unroll
        for (int f = 0; f < FF; ++f) {
            wzr[f] = g_cwz[f * OO + lane];
            whr[f] = g_cwh[f * OO + lane];
        }
        const float bz_ = g_cbz[lane];
        const float bh_ = g_cbh[lane];

        int base;
        if (lane == 0) base = (int)atomicAdd(&g_node_ctr, 2u);
        base = __shfl_sync(FULL, base, 0);
        Prolog pA, pB;
        if (base < NN) {                     // NN even -> base+1 valid too
            pA = load_prolog(base, lane, x);
            pB = load_prolog(base + 1, lane, x);
        }

        while (base < NN) {
            // -------- gather both nodes (prologue + self row resolved) -----
            #pragma unroll
            for (int i = 0; i < 2; ++i) {
                const Prolog& pr = (i == 0) ? pA : pB;
                const int node = base + i;
                float4 acc = make_float4(0.f, 0.f, 0.f, 0.f);

                int ci = pr.ci; float wv = pr.wv;
                int deg4 = (pr.deg + 3) & ~3;
                for (int b = 0; b < deg4; b += 32) {
                    if (b) {                                  // rare: deg > 32
                        int raw = __ldg(&g_col[node * SLOTS + b + lane]);
                        int cl = raw < 0 ? 0 : (raw >= NN ? NN - 1 : raw);
                        float w2 = rsqrtf((float)(__ldg(&g_cnt[cl]) + 1));
                        ci = (b + lane < pr.deg) ? cl : 0;
                        wv = (b + lane < pr.deg) ? w2 : 0.f;
                    }
                    int nb = deg4 - b; if (nb > 32) nb = 32;
                    for (int k = 0; k < nb; k += 4) {
                        int   s0 = __shfl_sync(FULL, ci, k);
                        int   s1 = __shfl_sync(FULL, ci, k + 1);
                        int   s2 = __shfl_sync(FULL, ci, k + 2);
                        int   s3 = __shfl_sync(FULL, ci, k + 3);
                        float w0 = __shfl_sync(FULL, wv, k);
                        float w1 = __shfl_sync(FULL, wv, k + 1);
                        float w2 = __shfl_sync(FULL, wv, k + 2);
                        float w3 = __shfl_sync(FULL, wv, k + 3);
                        if (lane < 24) {
                            float4 v0 = __ldg((const float4*)(x + (size_t)s0 * FP) + lane);
                            float4 v1 = __ldg((const float4*)(x + (size_t)s1 * FP) + lane);
                            float4 v2 = __ldg((const float4*)(x + (size_t)s2 * FP) + lane);
                            float4 v3 = __ldg((const float4*)(x + (size_t)s3 * FP) + lane);
                            acc.x = fmaf(w0, v0.x, acc.x); acc.y = fmaf(w0, v0.y, acc.y);
                            acc.z = fmaf(w0, v0.z, acc.z); acc.w = fmaf(w0, v0.w, acc.w);
                            acc.x = fmaf(w1, v1.x, acc.x); acc.y = fmaf(w1, v1.y, acc.y);
                            acc.z = fmaf(w1, v1.z, acc.z); acc.w = fmaf(w1, v1.w, acc.w);
                            acc.x = fmaf(w2, v2.x, acc.x); acc.y = fmaf(w2, v2.y, acc.y);
                            acc.z = fmaf(w2, v2.z, acc.z); acc.w = fmaf(w2, v2.w, acc.w);
                            acc.x = fmaf(w3, v3.x, acc.x); acc.y = fmaf(w3, v3.y, acc.y);
                            acc.z = fmaf(w3, v3.z, acc.z); acc.w = fmaf(w3, v3.w, acc.w);
                        }
                    }
                }
                if (lane < 24) {              // agg = di*(acc + di*x_self)
                    float di = pr.di;
                    acc.x = di * fmaf(di, pr.xv.x, acc.x);
                    acc.y = di * fmaf(di, pr.xv.y, acc.y);
                    acc.z = di * fmaf(di, pr.xv.z, acc.z);
                    acc.w = di * fmaf(di, pr.xv.w, acc.w);
                    ((float4*)buf[warp][i])[lane] = acc;
                }
            }
            const int obase = base;
            __syncwarp();

            // -------- pop + prefetch NEXT pair BEFORE the GRU compute ------
            if (lane == 0) base = (int)atomicAdd(&g_node_ctr, 2u);
            base = __shfl_sync(FULL, base, 0);
            if (base < NN) {
                pA = load_prolog(base, lane, x);       // hidden by GRU below
                pB = load_prolog(base + 1, lane, x);
            }

            // -------- GRU + readout for both nodes (pure compute) ----------
            #pragma unroll
            for (int i = 0; i < 2; ++i) {
                const float* bw = buf[warp][i];
                unsigned long long zp[PP / 2], hp[PP / 2];
                {
                    unsigned long long bz2 = pack2(bz_, bz_);
                    unsigned long long bh2 = pack2(bh_, bh_);
                    #pragma unroll
                    for (int q = 0; q < PP / 2; ++q) { zp[q] = bz2; hp[q] = bh2; }
                }
                #pragma unroll
                for (int f = 0; f < FF; ++f) {
                    unsigned long long wz2 = pack2(wzr[f], wzr[f]);
                    unsigned long long wh2 = pack2(whr[f], whr[f]);
                    #pragma unroll
                    for (int j = 0; j < PP / 4; ++j) {    // LDS.128: two f32x2 pairs
                        ulonglong2 v = *(const ulonglong2*)&bw[f * PP + 4 * j];
                        zp[2*j]   = ffma2(v.x, wz2, zp[2*j]);
                        hp[2*j]   = ffma2(v.x, wh2, hp[2*j]);
                        zp[2*j+1] = ffma2(v.y, wz2, zp[2*j+1]);
                        hp[2*j+1] = ffma2(v.y, wh2, hp[2*j+1]);
                    }
                }
                // probs*(1-Z)*tanh(h), Z = 0.5 + 0.5*tanh(z/2)
                float hacc = 0.f;
                #pragma unroll
                for (int q = 0; q < PP / 2; ++q) {
                    float z0, z1, h0, h1;
                    unpack2(zp[q], z0, z1);
                    unpack2(hp[q], h0, h1);
                    float tz0 = htanh(0.5f * z0);
                    float tz1 = htanh(0.5f * z1);
                    float th0 = htanh(h0);
                    float th1 = htanh(h1);
                    hacc = fmaf(sp2[2 * q],     (1.f - tz0) * th0, hacc);
                    hacc = fmaf(sp2[2 * q + 1], (1.f - tz1) * th1, hacc);
                }
                hrb[warp][i][lane] = fmaxf(hacc, 0.f);   // relu, stage for readout
            }
            __syncwarp();

            // -------- readout via smem (no shfl chains): lanes 0..11 -------
            #pragma unroll
            for (int i = 0; i < 2; ++i) {
                if (lane < PP) {
                    const float* hv = hrb[warp][i];
                    const float* wrow = sow + lane * SOWP;
                    float v = sob[lane];
                    #pragma unroll
                    for (int k = 0; k < OO; k += 4) {
                        float4 h4 = *(const float4*)&hv[k];     // broadcast
                        float4 w4 = *(const float4*)&wrow[k];   // bank-padded
                        v = fmaf(h4.x, w4.x, v);
                        v = fmaf(h4.y, w4.y, v);
                        v = fmaf(h4.z, w4.z, v);
                        v = fmaf(h4.w, w4.w, v);
                    }
                    out[(obase + i) * PP + lane] = v;
                }
            }
            __syncwarp();                    // smem reads done before next pair
        }
    }
}

// ---------------------------------------------------------------------------
extern "C" void kernel_launch(void* const* d_in, const int* in_sizes, int n_in,
                              void* d_out, int out_size) {
    const float* x    = (const float*)d_in[0];
    const int*   ei   = (const int*)  d_in[1];
    const float* Wz   = (const float*)d_in[2];
    const float* bz   = (const float*)d_in[3];
    // d_in[4], d_in[5]: Wr, br — dead code (H == 0 kills the reset gate)
    const float* Wh   = (const float*)d_in[6];
    const float* bh   = (const float*)d_in[7];
    const float* lzw  = (const float*)d_in[8];
    const float* lzb  = (const float*)d_in[9];
    // d_in[10], d_in[11]: lr_w, lr_b — unused
    const float* lhw  = (const float*)d_in[12];
    const float* lhb  = (const float*)d_in[13];
    const float* att  = (const float*)d_in[14];
    const float* outw = (const float*)d_in[15];
    const float* outb = (const float*)d_in[16];
    float* out = (float*)d_out;

    fused_kernel<<<NBLK, NTHR>>>(x, ei, Wz, bz, Wh, bh, lzw, lzb, lhw, lhb,
                                 att, outw, outb, out);
}